// round 12
// baseline (speedup 1.0000x reference)
#include <cuda_runtime.h>
#include <cuda_bf16.h>
#include <math.h>

#define NCLS 9
#define CCH  768
#define PIX  131072     // 8 * 128 * 128 downsampled pixels
#define PLANE 16384     // 128*128
#define CT   3          // channels per k_sums tile (768 = 256 * 3)

// ---------------- scratch (device globals; no allocation allowed) -------------
__device__ float         g_sums_part[8 * NCLS * CCH];   // per-batch partial sums
__device__ int           g_counts[NCLS];
__device__ float         g_ph[NCLS * CCH];              // normalized prototypes
__device__ unsigned char g_labels[PIX];
__device__ float         g_d[NCLS * PIX];               // 4.7 MB logit matrix (pre-norm)
__device__ float         g_rssq_part[NCLS * 256];
__device__ float         g_scale[NCLS];
__device__ float         g_partials[512];
__device__ int           g_is_i32;

// ---------------- f32x2 packed helpers ----------------------------------------
__device__ __forceinline__ unsigned long long pack2(float x, float y) {
    unsigned long long d;
    asm("mov.b64 %0, {%1, %2};" : "=l"(d) : "f"(x), "f"(y));
    return d;
}
__device__ __forceinline__ void unpack2(unsigned long long v, float& x, float& y) {
    asm("mov.b64 {%0, %1}, %2;" : "=f"(x), "=f"(y) : "l"(v));
}
__device__ __forceinline__ unsigned long long ffma2(unsigned long long a,
                                                    unsigned long long b,
                                                    unsigned long long c) {
    unsigned long long d;
    asm("fma.rn.f32x2 %0, %1, %2, %3;" : "=l"(d) : "l"(a), "l"(b), "l"(c));
    return d;
}

// ---------------- K_init: zero counters + gt dtype probe ----------------------
__global__ void k_init(const int* __restrict__ gt32) {
    int tid = threadIdx.x;
    if (tid < NCLS) g_counts[tid] = 0;
    // int64 gt (little-endian): odd 32-bit words are all 0.
    // int32 gt: odd words are labels in [0,9): P(all 2048 zero) ~ (1/9)^2048.
    int f = 0;
    for (int i = tid; i < 2048; i += 256) f |= gt32[2 * i + 1];
    __shared__ int sf;
    if (tid == 0) sf = 0;
    __syncthreads();
    if (f) atomicOr(&sf, 1);
    __syncthreads();
    if (tid == 0) g_is_i32 = (sf != 0);
}

// ---------------- K_dummy: keeps ncu capture slot (launch idx 3) on k_sums -----
__global__ void k_dummy() {}

// ---------------- K0: downsampled labels + histogram ---------------------------
__global__ void k_labels(const int* __restrict__ gt32) {
    __shared__ int sh[NCLS];
    int tid = threadIdx.x;
    if (tid < NCLS) sh[tid] = 0;
    __syncthreads();
    int n = blockIdx.x * 256 + tid;                 // grid = 512 blocks
    int b = n >> 14, r = n & (PLANE - 1);
    int h = r >> 7, w = r & 127;
    int idx = b * 262144 + h * 2048 + w * 4;        // gt[b, 4h, 4w] element index
    int lab = g_is_i32 ? gt32[idx] : gt32[2 * idx]; // int64: low word
    g_labels[n] = (unsigned char)lab;
    atomicAdd(&sh[lab], 1);
    __syncthreads();
    if (tid < NCLS) atomicAdd(&g_counts[tid], sh[tid]);
}

// ---------------- K1: per-class channel sums (register one-hot accumulate) -----
// grid = 2048: bid = b + 8*ctile (ctile in [0,256), CT=3 channels each).
// Each block owns g_sums_part[b][*][c0..c0+2] exclusively: no atomics.
// DEPTH-2 software pipeline: two 64-px groups' loads in flight at all times
// (~24.6 KB/SM in-flight vs the ~25.6 KB needed to cover DRAM latency).
// Masks via compare/select in registers (the L1-conflicting smem LUT measured
// worse: per-lane-divergent LDS hit 86% L1 in R11).
__global__ void __launch_bounds__(256, 2) k_sums(const float* __restrict__ feat) {
    int bid = blockIdx.x;
    int b = bid & 7;
    int c0 = (bid >> 3) * CT;
    int tid = threadIdx.x, w = tid >> 5, lane = tid & 31;
    const float* base = feat + (size_t)(b * CCH + c0) * PLANE;
    const unsigned short* lab16 = (const unsigned short*)(g_labels + b * PLANE);

    unsigned long long acc[NCLS][CT];
#pragma unroll
    for (int k = 0; k < NCLS; k++)
#pragma unroll
        for (int j = 0; j < CT; j++) acc[k][j] = 0ULL;

    int pix0 = w * 2048 + lane * 2;

    // prefetch groups 0 and 1
    unsigned int u0 = lab16[pix0 >> 1];
    float2 v0[CT];
#pragma unroll
    for (int j = 0; j < CT; j++) v0[j] = *(const float2*)(base + j * PLANE + pix0);
    unsigned int u1 = lab16[(pix0 + 64) >> 1];
    float2 v1[CT];
#pragma unroll
    for (int j = 0; j < CT; j++) v1[j] = *(const float2*)(base + j * PLANE + pix0 + 64);

#pragma unroll 2
    for (int g = 0; g < 32; ++g) {
        // consume oldest buffer
        unsigned int u = u0;
        float2 v[CT];
#pragma unroll
        for (int j = 0; j < CT; j++) v[j] = v0[j];
        // rotate: buffer1 -> buffer0
        u0 = u1;
#pragma unroll
        for (int j = 0; j < CT; j++) v0[j] = v1[j];
        // issue loads for g+2 BEFORE the FMA block
        if (g < 30) {
            int p2 = pix0 + (g + 2) * 64;
            u1 = lab16[p2 >> 1];
#pragma unroll
            for (int j = 0; j < CT; j++) v1[j] = *(const float2*)(base + j * PLANE + p2);
        }
        unsigned long long vv[CT];
#pragma unroll
        for (int j = 0; j < CT; j++) vv[j] = pack2(v[j].x, v[j].y);
        int l0 = u & 0xff, l1 = (u >> 8) & 0xff;
#pragma unroll
        for (int k = 0; k < NCLS; k++) {
            float m0 = (l0 == k) ? 1.0f : 0.0f;
            float m1 = (l1 == k) ? 1.0f : 0.0f;
            unsigned long long mk = pack2(m0, m1);
#pragma unroll
            for (int j = 0; j < CT; j++) acc[k][j] = ffma2(mk, vv[j], acc[k][j]);
        }
    }

    __shared__ float sred[8][NCLS * CT];
#pragma unroll
    for (int k = 0; k < NCLS; k++)
#pragma unroll
        for (int j = 0; j < CT; j++) {
            float lo, hi;
            unpack2(acc[k][j], lo, hi);
            float s = lo + hi;
#pragma unroll
            for (int off = 16; off; off >>= 1) s += __shfl_xor_sync(0xffffffffu, s, off);
            if (lane == 0) sred[w][k * CT + j] = s;
        }
    __syncthreads();
    if (tid < NCLS * CT) {
        float t = 0.0f;
#pragma unroll
        for (int w2 = 0; w2 < 8; w2++) t += sred[w2][tid];
        int k = tid / CT, j = tid % CT;
        g_sums_part[b * NCLS * CCH + k * CCH + c0 + j] = t;
    }
}

// ---------------- K2: prototype EMA + L2 normalize ------------------------------
// 9 blocks (one per class), 256 threads; each thread owns 3 channels.
__global__ void k_protos(const float* __restrict__ proto0) {
    __shared__ float sred[256];
    int k = blockIdx.x;
    int tid = threadIdx.x;
    int cnt = g_counts[k];
    float inv = 0.99f / fmaxf((float)cnt, 1.0f);
    bool present = (cnt > 0);
    float vals[3];
    float ssq = 0.0f;
#pragma unroll
    for (int i = 0; i < 3; i++) {
        int c = tid + 256 * i;
        float s = 0.0f;
#pragma unroll
        for (int b = 0; b < 8; b++) s += g_sums_part[b * NCLS * CCH + k * CCH + c];
        float p0 = proto0[k * CCH + c];
        float u = present ? (inv * s + 0.01f * p0) : p0;
        vals[i] = u;
        ssq += u * u;
    }
    sred[tid] = ssq;
    __syncthreads();
#pragma unroll
    for (int s = 128; s; s >>= 1) {
        if (tid < s) sred[tid] += sred[tid + s];
        __syncthreads();
    }
    float r = 1.0f / fmaxf(sqrtf(sred[0]), 1e-12f);
#pragma unroll
    for (int i = 0; i < 3; i++) g_ph[k * CCH + tid + 256 * i] = vals[i] * r;
}

// ---------------- K3: d[k,n] = P_hat @ F + per-class sumsq partials -------------
// block = 256 threads (8 warps). Warp pair (wp, wp+4) shares 128 px; halves
// split the 768 channels (384 each). 512 px/block, grid = 256 blocks.
// Prototype table transposed spt[c][12] (9 + 3 pad floats, 48B rows): each
// channel needs 3 broadcast LDS.128. Static smem only; spt region is reused
// for the cross-half accumulators after a sync (peak 36.9 KB).
__global__ void __launch_bounds__(256) k_logits(const float* __restrict__ feat) {
    __shared__ float smemf[CCH * 12];           // 36864 B, dual-purpose
    float*  spt  = smemf;                       // [768][12] during channel loop
    float4* sacc = (float4*)smemf;              // [4][9][32] float4 afterwards
    float*  swq  = smemf + 4 * NCLS * 32 * 4;   // [4][9] (offset 4608 floats)

    int tid = threadIdx.x;
    for (int i = tid; i < NCLS * CCH; i += 256) {
        int c = i / NCLS, k = i - c * NCLS;
        spt[c * 12 + k] = g_ph[k * CCH + c];
    }
    __syncthreads();

    int w = tid >> 5, lane = tid & 31;
    int wpair = w & 3, half = w >> 2;
    int px0 = blockIdx.x * 512 + wpair * 128;
    int b = px0 >> 14;
    int spx = (px0 & (PLANE - 1)) + lane * 4;
    const float* fb = feat + (size_t)b * CCH * PLANE + spx;
    int c0 = half * 384;

    unsigned long long alo[NCLS], ahi[NCLS];
#pragma unroll
    for (int k = 0; k < NCLS; k++) { alo[k] = 0ULL; ahi[k] = 0ULL; }

    // prefetch first 4 channels
    float4 vnext[4];
#pragma unroll
    for (int u = 0; u < 4; u++)
        vnext[u] = *(const float4*)(fb + (size_t)(c0 + u) * PLANE);

#pragma unroll 1
    for (int cc = 0; cc < 384; cc += 4) {
        float4 v[4];
#pragma unroll
        for (int u = 0; u < 4; u++) v[u] = vnext[u];
        if (cc < 380) {
#pragma unroll
            for (int u = 0; u < 4; u++)
                vnext[u] = *(const float4*)(fb + (size_t)(c0 + cc + 4 + u) * PLANE);
        }
#pragma unroll
        for (int u = 0; u < 4; u++) {
            unsigned long long vlo = pack2(v[u].x, v[u].y);
            unsigned long long vhi = pack2(v[u].z, v[u].w);
            const float4* pr = (const float4*)(spt + (c0 + cc + u) * 12);
            float4 p03 = pr[0], p47 = pr[1], p8x = pr[2];
            unsigned long long q;
            q = pack2(p03.x, p03.x); alo[0] = ffma2(q, vlo, alo[0]); ahi[0] = ffma2(q, vhi, ahi[0]);
            q = pack2(p03.y, p03.y); alo[1] = ffma2(q, vlo, alo[1]); ahi[1] = ffma2(q, vhi, ahi[1]);
            q = pack2(p03.z, p03.z); alo[2] = ffma2(q, vlo, alo[2]); ahi[2] = ffma2(q, vhi, ahi[2]);
            q = pack2(p03.w, p03.w); alo[3] = ffma2(q, vlo, alo[3]); ahi[3] = ffma2(q, vhi, ahi[3]);
            q = pack2(p47.x, p47.x); alo[4] = ffma2(q, vlo, alo[4]); ahi[4] = ffma2(q, vhi, ahi[4]);
            q = pack2(p47.y, p47.y); alo[5] = ffma2(q, vlo, alo[5]); ahi[5] = ffma2(q, vhi, ahi[5]);
            q = pack2(p47.z, p47.z); alo[6] = ffma2(q, vlo, alo[6]); ahi[6] = ffma2(q, vhi, ahi[6]);
            q = pack2(p47.w, p47.w); alo[7] = ffma2(q, vlo, alo[7]); ahi[7] = ffma2(q, vhi, ahi[7]);
            q = pack2(p8x.x, p8x.x); alo[8] = ffma2(q, vlo, alo[8]); ahi[8] = ffma2(q, vhi, ahi[8]);
        }
    }

    __syncthreads();   // all warps done reading spt; region becomes sacc/swq
    if (half == 1) {
#pragma unroll
        for (int k = 0; k < NCLS; k++) {
            float x0, x1, x2, x3;
            unpack2(alo[k], x0, x1);
            unpack2(ahi[k], x2, x3);
            sacc[(wpair * NCLS + k) * 32 + lane] = make_float4(x0, x1, x2, x3);
        }
    }
    __syncthreads();
    if (half == 0) {
#pragma unroll
        for (int k = 0; k < NCLS; k++) {
            float x0, x1, x2, x3;
            unpack2(alo[k], x0, x1);
            unpack2(ahi[k], x2, x3);
            float4 o2 = sacc[(wpair * NCLS + k) * 32 + lane];
            x0 += o2.x; x1 += o2.y; x2 += o2.z; x3 += o2.w;
            *(float4*)(g_d + (size_t)k * PIX + px0 + lane * 4) =
                make_float4(x0, x1, x2, x3);
            float q = x0 * x0 + x1 * x1 + x2 * x2 + x3 * x3;
#pragma unroll
            for (int off = 16; off; off >>= 1) q += __shfl_xor_sync(0xffffffffu, q, off);
            if (lane == 0) swq[wpair * NCLS + k] = q;
        }
    }
    __syncthreads();
    if (tid < NCLS) {
        float q = swq[0 * NCLS + tid] + swq[1 * NCLS + tid] +
                  swq[2 * NCLS + tid] + swq[3 * NCLS + tid];
        g_rssq_part[tid * 256 + blockIdx.x] = q;
    }
}

// ---------------- K3b: per-class scale = 1/(max(||row||,eps)*T) -----------------
__global__ void k_scale() {
    int tid = threadIdx.x;
    int k = tid >> 5, lane = tid & 31;
    if (k >= NCLS) return;
    float s = 0.0f;
#pragma unroll
    for (int j = 0; j < 8; j++) s += g_rssq_part[k * 256 + lane + 32 * j];
#pragma unroll
    for (int off = 16; off; off >>= 1) s += __shfl_xor_sync(0xffffffffu, s, off);
    if (lane == 0) g_scale[k] = 1.0f / (fmaxf(sqrtf(s), 1e-12f) * 0.1f);
}

// ---------------- K4: log-softmax over classes, pick label, block partial -------
__global__ void __launch_bounds__(256) k_loss() {
    __shared__ float ssc[NCLS];
    __shared__ float sred[256];
    int tid = threadIdx.x;
    if (tid < NCLS) ssc[tid] = g_scale[tid];
    __syncthreads();
    int n = blockIdx.x * 256 + tid;
    float x[NCLS];
    float m = -1e30f;
#pragma unroll
    for (int k = 0; k < NCLS; k++) {
        x[k] = g_d[(size_t)k * PIX + n] * ssc[k];
        m = fmaxf(m, x[k]);
    }
    float se = 0.0f;
#pragma unroll
    for (int k = 0; k < NCLS; k++) se += __expf(x[k] - m);
    float lse = m + __logf(se);
    int lab = g_labels[n];
    sred[tid] = x[lab] - lse;
    __syncthreads();
#pragma unroll
    for (int s = 128; s; s >>= 1) {
        if (tid < s) sred[tid] += sred[tid + s];
        __syncthreads();
    }
    if (tid == 0) g_partials[blockIdx.x] = sred[0];
}

// ---------------- K5: final deterministic reduction -----------------------------
__global__ void k_final(float* __restrict__ out) {
    __shared__ float sred[256];
    int tid = threadIdx.x;
    sred[tid] = g_partials[tid] + g_partials[tid + 256];
    __syncthreads();
#pragma unroll
    for (int s = 128; s; s >>= 1) {
        if (tid < s) sred[tid] += sred[tid + s];
        __syncthreads();
    }
    if (tid == 0) out[0] = -sred[0] * (1.0f / (float)PIX);
}

// ---------------- launch --------------------------------------------------------
extern "C" void kernel_launch(void* const* d_in, const int* in_sizes, int n_in,
                              void* d_out, int out_size) {
    const float* feat   = (const float*)d_in[0];
    const int*   gt32   = (const int*)d_in[1];   // int32 or int64, probed
    const float* proto0 = (const float*)d_in[2];
    float* out = (float*)d_out;

    k_init  <<<1,    256>>>(gt32);
    k_labels<<<512,  256>>>(gt32);
    k_dummy <<<1,    32>>>();                    // keeps ncu slot on k_sums
    k_sums  <<<2048, 256>>>(feat);
    k_protos<<<NCLS, 256>>>(proto0);
    k_logits<<<256,  256>>>(feat);
    k_scale <<<1,    288>>>();
    k_loss  <<<512,  256>>>();
    k_final <<<1,    256>>>(out);
}

// round 14
// speedup vs baseline: 1.2806x; 1.2806x over previous
#include <cuda_runtime.h>
#include <cuda_bf16.h>
#include <math.h>

#define NCLS 9
#define CCH  768
#define PIX  131072     // 8 * 128 * 128 downsampled pixels
#define PLANE 16384     // 128*128
#define CT   3          // channels per k_sums tile (768 = 256 * 3)

// ---------------- scratch (device globals; no allocation allowed) -------------
__device__ float         g_sums_part[8 * NCLS * CCH];   // per-batch partial sums
__device__ int           g_counts[NCLS];
__device__ float         g_ph[NCLS * CCH];              // normalized prototypes
__device__ unsigned char g_labels[PIX];
__device__ float         g_d[NCLS * PIX];               // 4.7 MB logit matrix (pre-norm)
__device__ float         g_rssq_part[NCLS * 256];
__device__ float         g_scale[NCLS];
__device__ float         g_partials[512];
__device__ int           g_is_i32;

// ---------------- f32x2 packed helpers ----------------------------------------
__device__ __forceinline__ unsigned long long pack2(float x, float y) {
    unsigned long long d;
    asm("mov.b64 %0, {%1, %2};" : "=l"(d) : "f"(x), "f"(y));
    return d;
}
__device__ __forceinline__ void unpack2(unsigned long long v, float& x, float& y) {
    asm("mov.b64 {%0, %1}, %2;" : "=f"(x), "=f"(y) : "l"(v));
}
__device__ __forceinline__ unsigned long long ffma2(unsigned long long a,
                                                    unsigned long long b,
                                                    unsigned long long c) {
    unsigned long long d;
    asm("fma.rn.f32x2 %0, %1, %2, %3;" : "=l"(d) : "l"(a), "l"(b), "l"(c));
    return d;
}

// ---------------- K_init: zero counters + gt dtype probe ----------------------
__global__ void k_init(const int* __restrict__ gt32) {
    int tid = threadIdx.x;
    if (tid < NCLS) g_counts[tid] = 0;
    // int64 gt (little-endian): odd 32-bit words are all 0.
    // int32 gt: odd words are labels in [0,9): P(all 2048 zero) ~ (1/9)^2048.
    int f = 0;
    for (int i = tid; i < 2048; i += 256) f |= gt32[2 * i + 1];
    __shared__ int sf;
    if (tid == 0) sf = 0;
    __syncthreads();
    if (f) atomicOr(&sf, 1);
    __syncthreads();
    if (tid == 0) g_is_i32 = (sf != 0);
}

// ---------------- K_dummy: keeps ncu capture slot (launch idx 3) on k_sums -----
__global__ void k_dummy() {}

// ---------------- K0: downsampled labels + histogram ---------------------------
__global__ void k_labels(const int* __restrict__ gt32) {
    __shared__ int sh[NCLS];
    int tid = threadIdx.x;
    if (tid < NCLS) sh[tid] = 0;
    __syncthreads();
    int n = blockIdx.x * 256 + tid;                 // grid = 512 blocks
    int b = n >> 14, r = n & (PLANE - 1);
    int h = r >> 7, w = r & 127;
    int idx = b * 262144 + h * 2048 + w * 4;        // gt[b, 4h, 4w] element index
    int lab = g_is_i32 ? gt32[idx] : gt32[2 * idx]; // int64: low word
    g_labels[n] = (unsigned char)lab;
    atomicAdd(&sh[lab], 1);
    __syncthreads();
    if (tid < NCLS) atomicAdd(&g_counts[tid], sh[tid]);
}

// ---------------- K1: per-class channel sums (register one-hot accumulate) -----
// grid = 2048: bid = b + 8*ctile (ctile in [0,256), CT=3 channels each).
// Each block owns g_sums_part[b][*][c0..c0+2] exclusively: no atomics.
// R7 structure (single prefetch buffer, no rotation) but WIDENED to float4:
// 4 pixels/lane -> 1536 B in flight per warp-group (2x R7) with no extra
// buffer-management instructions. Rotation (R12) and smem LUT (R11) both
// measured worse; width is the safe way to add latency coverage.
__global__ void __launch_bounds__(256, 2) k_sums(const float* __restrict__ feat) {
    int bid = blockIdx.x;
    int b = bid & 7;
    int c0 = (bid >> 3) * CT;
    int tid = threadIdx.x, w = tid >> 5, lane = tid & 31;
    const float* base = feat + (size_t)(b * CCH + c0) * PLANE;
    const unsigned int* lab32 = (const unsigned int*)(g_labels + b * PLANE);

    unsigned long long acc[NCLS][CT];
#pragma unroll
    for (int k = 0; k < NCLS; k++)
#pragma unroll
        for (int j = 0; j < CT; j++) acc[k][j] = 0ULL;

    int pix0 = w * 2048 + lane * 4;

    // prefetch group 0 (128 px per warp per group)
    unsigned int un = lab32[pix0 >> 2];
    float4 vn[CT];
#pragma unroll
    for (int j = 0; j < CT; j++) vn[j] = *(const float4*)(base + j * PLANE + pix0);

#pragma unroll 2
    for (int g = 0; g < 16; ++g) {
        unsigned int u = un;
        float4 v[CT];
#pragma unroll
        for (int j = 0; j < CT; j++) v[j] = vn[j];
        if (g < 15) {
            int p2 = pix0 + (g + 1) * 128;
            un = lab32[p2 >> 2];
#pragma unroll
            for (int j = 0; j < CT; j++) vn[j] = *(const float4*)(base + j * PLANE + p2);
        }
        unsigned long long vlo[CT], vhi[CT];
#pragma unroll
        for (int j = 0; j < CT; j++) {
            vlo[j] = pack2(v[j].x, v[j].y);
            vhi[j] = pack2(v[j].z, v[j].w);
        }
        int l0 = u & 0xff, l1 = (u >> 8) & 0xff;
        int l2 = (u >> 16) & 0xff, l3 = (u >> 24) & 0xff;
#pragma unroll
        for (int k = 0; k < NCLS; k++) {
            unsigned long long m01 = pack2((l0 == k) ? 1.0f : 0.0f,
                                           (l1 == k) ? 1.0f : 0.0f);
            unsigned long long m23 = pack2((l2 == k) ? 1.0f : 0.0f,
                                           (l3 == k) ? 1.0f : 0.0f);
#pragma unroll
            for (int j = 0; j < CT; j++) {
                acc[k][j] = ffma2(m01, vlo[j], acc[k][j]);
                acc[k][j] = ffma2(m23, vhi[j], acc[k][j]);
            }
        }
    }

    __shared__ float sred[8][NCLS * CT];
#pragma unroll
    for (int k = 0; k < NCLS; k++)
#pragma unroll
        for (int j = 0; j < CT; j++) {
            float lo, hi;
            unpack2(acc[k][j], lo, hi);
            float s = lo + hi;
#pragma unroll
            for (int off = 16; off; off >>= 1) s += __shfl_xor_sync(0xffffffffu, s, off);
            if (lane == 0) sred[w][k * CT + j] = s;
        }
    __syncthreads();
    if (tid < NCLS * CT) {
        float t = 0.0f;
#pragma unroll
        for (int w2 = 0; w2 < 8; w2++) t += sred[w2][tid];
        int k = tid / CT, j = tid % CT;
        g_sums_part[b * NCLS * CCH + k * CCH + c0 + j] = t;
    }
}

// ---------------- K2: prototype EMA + L2 normalize ------------------------------
// 9 blocks (one per class), 256 threads; each thread owns 3 channels.
__global__ void k_protos(const float* __restrict__ proto0) {
    __shared__ float sred[256];
    int k = blockIdx.x;
    int tid = threadIdx.x;
    int cnt = g_counts[k];
    float inv = 0.99f / fmaxf((float)cnt, 1.0f);
    bool present = (cnt > 0);
    float vals[3];
    float ssq = 0.0f;
#pragma unroll
    for (int i = 0; i < 3; i++) {
        int c = tid + 256 * i;
        float s = 0.0f;
#pragma unroll
        for (int b = 0; b < 8; b++) s += g_sums_part[b * NCLS * CCH + k * CCH + c];
        float p0 = proto0[k * CCH + c];
        float u = present ? (inv * s + 0.01f * p0) : p0;
        vals[i] = u;
        ssq += u * u;
    }
    sred[tid] = ssq;
    __syncthreads();
#pragma unroll
    for (int s = 128; s; s >>= 1) {
        if (tid < s) sred[tid] += sred[tid + s];
        __syncthreads();
    }
    float r = 1.0f / fmaxf(sqrtf(sred[0]), 1e-12f);
#pragma unroll
    for (int i = 0; i < 3; i++) g_ph[k * CCH + tid + 256 * i] = vals[i] * r;
}

// ---------------- K3: d[k,n] = P_hat @ F + per-class sumsq partials -------------
// block = 256 threads (8 warps). Warp pair (wp, wp+4) shares 128 px; halves
// split the 768 channels (384 each). 512 px/block, grid = 256 blocks.
// Prototype table transposed spt[c][12] (9 + 3 pad floats, 48B rows): each
// channel needs 3 broadcast LDS.128. Static smem only; spt region is reused
// for the cross-half accumulators after a sync (peak 36.9 KB).
__global__ void __launch_bounds__(256) k_logits(const float* __restrict__ feat) {
    __shared__ float smemf[CCH * 12];           // 36864 B, dual-purpose
    float*  spt  = smemf;                       // [768][12] during channel loop
    float4* sacc = (float4*)smemf;              // [4][9][32] float4 afterwards
    float*  swq  = smemf + 4 * NCLS * 32 * 4;   // [4][9] (offset 4608 floats)

    int tid = threadIdx.x;
    for (int i = tid; i < NCLS * CCH; i += 256) {
        int c = i / NCLS, k = i - c * NCLS;
        spt[c * 12 + k] = g_ph[k * CCH + c];
    }
    __syncthreads();

    int w = tid >> 5, lane = tid & 31;
    int wpair = w & 3, half = w >> 2;
    int px0 = blockIdx.x * 512 + wpair * 128;
    int b = px0 >> 14;
    int spx = (px0 & (PLANE - 1)) + lane * 4;
    const float* fb = feat + (size_t)b * CCH * PLANE + spx;
    int c0 = half * 384;

    unsigned long long alo[NCLS], ahi[NCLS];
#pragma unroll
    for (int k = 0; k < NCLS; k++) { alo[k] = 0ULL; ahi[k] = 0ULL; }

    // prefetch first 4 channels
    float4 vnext[4];
#pragma unroll
    for (int u = 0; u < 4; u++)
        vnext[u] = *(const float4*)(fb + (size_t)(c0 + u) * PLANE);

#pragma unroll 1
    for (int cc = 0; cc < 384; cc += 4) {
        float4 v[4];
#pragma unroll
        for (int u = 0; u < 4; u++) v[u] = vnext[u];
        if (cc < 380) {
#pragma unroll
            for (int u = 0; u < 4; u++)
                vnext[u] = *(const float4*)(fb + (size_t)(c0 + cc + 4 + u) * PLANE);
        }
#pragma unroll
        for (int u = 0; u < 4; u++) {
            unsigned long long vlo = pack2(v[u].x, v[u].y);
            unsigned long long vhi = pack2(v[u].z, v[u].w);
            const float4* pr = (const float4*)(spt + (c0 + cc + u) * 12);
            float4 p03 = pr[0], p47 = pr[1], p8x = pr[2];
            unsigned long long q;
            q = pack2(p03.x, p03.x); alo[0] = ffma2(q, vlo, alo[0]); ahi[0] = ffma2(q, vhi, ahi[0]);
            q = pack2(p03.y, p03.y); alo[1] = ffma2(q, vlo, alo[1]); ahi[1] = ffma2(q, vhi, ahi[1]);
            q = pack2(p03.z, p03.z); alo[2] = ffma2(q, vlo, alo[2]); ahi[2] = ffma2(q, vhi, ahi[2]);
            q = pack2(p03.w, p03.w); alo[3] = ffma2(q, vlo, alo[3]); ahi[3] = ffma2(q, vhi, ahi[3]);
            q = pack2(p47.x, p47.x); alo[4] = ffma2(q, vlo, alo[4]); ahi[4] = ffma2(q, vhi, ahi[4]);
            q = pack2(p47.y, p47.y); alo[5] = ffma2(q, vlo, alo[5]); ahi[5] = ffma2(q, vhi, ahi[5]);
            q = pack2(p47.z, p47.z); alo[6] = ffma2(q, vlo, alo[6]); ahi[6] = ffma2(q, vhi, ahi[6]);
            q = pack2(p47.w, p47.w); alo[7] = ffma2(q, vlo, alo[7]); ahi[7] = ffma2(q, vhi, ahi[7]);
            q = pack2(p8x.x, p8x.x); alo[8] = ffma2(q, vlo, alo[8]); ahi[8] = ffma2(q, vhi, ahi[8]);
        }
    }

    __syncthreads();   // all warps done reading spt; region becomes sacc/swq
    if (half == 1) {
#pragma unroll
        for (int k = 0; k < NCLS; k++) {
            float x0, x1, x2, x3;
            unpack2(alo[k], x0, x1);
            unpack2(ahi[k], x2, x3);
            sacc[(wpair * NCLS + k) * 32 + lane] = make_float4(x0, x1, x2, x3);
        }
    }
    __syncthreads();
    if (half == 0) {
#pragma unroll
        for (int k = 0; k < NCLS; k++) {
            float x0, x1, x2, x3;
            unpack2(alo[k], x0, x1);
            unpack2(ahi[k], x2, x3);
            float4 o2 = sacc[(wpair * NCLS + k) * 32 + lane];
            x0 += o2.x; x1 += o2.y; x2 += o2.z; x3 += o2.w;
            *(float4*)(g_d + (size_t)k * PIX + px0 + lane * 4) =
                make_float4(x0, x1, x2, x3);
            float q = x0 * x0 + x1 * x1 + x2 * x2 + x3 * x3;
#pragma unroll
            for (int off = 16; off; off >>= 1) q += __shfl_xor_sync(0xffffffffu, q, off);
            if (lane == 0) swq[wpair * NCLS + k] = q;
        }
    }
    __syncthreads();
    if (tid < NCLS) {
        float q = swq[0 * NCLS + tid] + swq[1 * NCLS + tid] +
                  swq[2 * NCLS + tid] + swq[3 * NCLS + tid];
        g_rssq_part[tid * 256 + blockIdx.x] = q;
    }
}

// ---------------- K3b: per-class scale = 1/(max(||row||,eps)*T) -----------------
__global__ void k_scale() {
    int tid = threadIdx.x;
    int k = tid >> 5, lane = tid & 31;
    if (k >= NCLS) return;
    float s = 0.0f;
#pragma unroll
    for (int j = 0; j < 8; j++) s += g_rssq_part[k * 256 + lane + 32 * j];
#pragma unroll
    for (int off = 16; off; off >>= 1) s += __shfl_xor_sync(0xffffffffu, s, off);
    if (lane == 0) g_scale[k] = 1.0f / (fmaxf(sqrtf(s), 1e-12f) * 0.1f);
}

// ---------------- K4: log-softmax over classes, pick label, block partial -------
__global__ void __launch_bounds__(256) k_loss() {
    __shared__ float ssc[NCLS];
    __shared__ float sred[256];
    int tid = threadIdx.x;
    if (tid < NCLS) ssc[tid] = g_scale[tid];
    __syncthreads();
    int n = blockIdx.x * 256 + tid;
    float x[NCLS];
    float m = -1e30f;
#pragma unroll
    for (int k = 0; k < NCLS; k++) {
        x[k] = g_d[(size_t)k * PIX + n] * ssc[k];
        m = fmaxf(m, x[k]);
    }
    float se = 0.0f;
#pragma unroll
    for (int k = 0; k < NCLS; k++) se += __expf(x[k] - m);
    float lse = m + __logf(se);
    int lab = g_labels[n];
    sred[tid] = x[lab] - lse;
    __syncthreads();
#pragma unroll
    for (int s = 128; s; s >>= 1) {
        if (tid < s) sred[tid] += sred[tid + s];
        __syncthreads();
    }
    if (tid == 0) g_partials[blockIdx.x] = sred[0];
}

// ---------------- K5: final deterministic reduction -----------------------------
__global__ void k_final(float* __restrict__ out) {
    __shared__ float sred[256];
    int tid = threadIdx.x;
    sred[tid] = g_partials[tid] + g_partials[tid + 256];
    __syncthreads();
#pragma unroll
    for (int s = 128; s; s >>= 1) {
        if (tid < s) sred[tid] += sred[tid + s];
        __syncthreads();
    }
    if (tid == 0) out[0] = -sred[0] * (1.0f / (float)PIX);
}

// ---------------- launch --------------------------------------------------------
extern "C" void kernel_launch(void* const* d_in, const int* in_sizes, int n_in,
                              void* d_out, int out_size) {
    const float* feat   = (const float*)d_in[0];
    const int*   gt32   = (const int*)d_in[1];   // int32 or int64, probed
    const float* proto0 = (const float*)d_in[2];
    float* out = (float*)d_out;

    k_init  <<<1,    256>>>(gt32);
    k_labels<<<512,  256>>>(gt32);
    k_dummy <<<1,    32>>>();                    // keeps ncu slot on k_sums
    k_sums  <<<2048, 256>>>(feat);
    k_protos<<<NCLS, 256>>>(proto0);
    k_logits<<<256,  256>>>(feat);
    k_scale <<<1,    288>>>();
    k_loss  <<<512,  256>>>();
    k_final <<<1,    256>>>(out);
}